// round 4
// baseline (speedup 1.0000x reference)
#include <cuda_runtime.h>

#define TT 512
#define IN 64
#define HH 16
#define NC 6
#define NB 1024
#define G4 64

typedef unsigned long long u64;

__device__ __forceinline__ float fast_tanh(float x) {
    float r; asm("tanh.approx.f32 %0, %1;" : "=f"(r) : "f"(x)); return r;
}
__device__ __forceinline__ float fast_sig(float x) {
    return fmaf(fast_tanh(0.5f * x), 0.5f, 0.5f);
}
__device__ __forceinline__ void ffma2(u64& a, u64 b, u64 c) {
    asm("fma.rn.f32x2 %0, %1, %2, %0;" : "+l"(a) : "l"(b), "l"(c));
}
__device__ __forceinline__ u64 fadd2(u64 a, u64 b) {
    u64 r; asm("add.rn.f32x2 %0, %1, %2;" : "=l"(r) : "l"(a), "l"(b)); return r;
}
__device__ __forceinline__ float2 upk(u64 v) {
    float2 r; asm("mov.b64 {%0, %1}, %2;" : "=f"(r.x), "=f"(r.y) : "l"(v)); return r;
}
__device__ __forceinline__ u64 pk(float x, float y) {
    u64 r; asm("mov.b64 %0, {%1, %2};" : "=l"(r) : "f"(x), "f"(y)); return r;
}

// 128 MB scratch: gates_x[b*TT + t][g]  (g in standard [i,f,g,o] order)
__device__ float g_gates[(size_t)NB * TT * G4];

// ---------------- Phase 1: gates_x = x @ w_ih^T + b_ih + b_hh ----------------
// One warp per 64 consecutive (b,t) tasks; lane owns gates (2*lane, 2*lane+1).
#define K1_WARPS_PER_BLOCK 4
#define K1_ITERS 64
#define K1_GRID ((NB * TT) / (K1_WARPS_PER_BLOCK * K1_ITERS))  // 2048

__global__ __launch_bounds__(128, 3)
void gates_kernel(const float* __restrict__ x,
                  const float* __restrict__ w_ih,
                  const float* __restrict__ b_ih,
                  const float* __restrict__ b_hh)
{
    const int lane = threadIdx.x & 31;
    const int w    = threadIdx.x >> 5;
    const int wg   = blockIdx.x * K1_WARPS_PER_BLOCK + w;
    const int g0   = 2 * lane, g1 = 2 * lane + 1;

    __shared__ __align__(16) u64 s_x[K1_WARPS_PER_BLOCK][2][32];

    u64 wA[32], wB[32];
    {
        const ulonglong2* p = (const ulonglong2*)(w_ih + g0 * IN);
        #pragma unroll
        for (int k = 0; k < 16; k++) { ulonglong2 v = p[k]; wA[2*k] = v.x; wA[2*k+1] = v.y; }
        p = (const ulonglong2*)(w_ih + g1 * IN);
        #pragma unroll
        for (int k = 0; k < 16; k++) { ulonglong2 v = p[k]; wB[2*k] = v.x; wB[2*k+1] = v.y; }
    }
    const float biasA = b_ih[g0] + b_hh[g0];
    const float biasB = b_ih[g1] + b_hh[g1];

    const size_t base = (size_t)wg * K1_ITERS;          // first task of this warp
    const float* xp = x + base * G4 + 2 * lane;
    float*       gp = g_gates + base * G4 + 2 * lane;

    u64 xv = *(const u64*)xp;                           // prefetch task 0
    #pragma unroll 2
    for (int it = 0; it < K1_ITERS; it++) {
        s_x[w][it & 1][lane] = xv;
        __syncwarp();
        if (it + 1 < K1_ITERS) xv = *(const u64*)(xp + (size_t)(it + 1) * G4);

        u64 a0 = pk(biasA, 0.f), a1 = 0ull, b0 = pk(biasB, 0.f), b1 = 0ull;
        const ulonglong2* xs = (const ulonglong2*)s_x[w][it & 1];
        #pragma unroll
        for (int k = 0; k < 16; k++) {
            ulonglong2 q = xs[k];                       // broadcast LDS.128
            ffma2(a0, wA[2*k],   q.x);
            ffma2(a1, wA[2*k+1], q.y);
            ffma2(b0, wB[2*k],   q.x);
            ffma2(b1, wB[2*k+1], q.y);
        }
        float2 pa = upk(fadd2(a0, a1));
        float2 pb = upk(fadd2(b0, b1));
        *(u64*)(gp + (size_t)it * G4) = pk(pa.x + pa.y, pb.x + pb.y);
    }
}

// ---------------- Phase 2: recurrence + fused FC ----------------
// One warp per batch element. Lane owns gates (lane, lane+32):
// lanes 0..15 -> (i_j, g_j), lanes 16..31 -> (f_j, o_j), j = lane & 15.
// ALL lanes redundantly maintain c_j, h_j (partner shfl supplies the missing gates).
__global__ __launch_bounds__(32, 8)
void rec_kernel(const float* __restrict__ w_hh,
                const float* __restrict__ w_fc,
                const float* __restrict__ b_fc,
                float* __restrict__ out)
{
    const int b    = blockIdx.x;
    const int lane = threadIdx.x;
    const int glo  = lane, ghi = lane + 32;

    __shared__ __align__(16) float s_h[HH];

    u64 hlo[8], hhi[8];
    {
        const ulonglong2* p = (const ulonglong2*)(w_hh + glo * HH);
        #pragma unroll
        for (int k = 0; k < 4; k++) { ulonglong2 v = p[k]; hlo[2*k] = v.x; hlo[2*k+1] = v.y; }
        p = (const ulonglong2*)(w_hh + ghi * HH);
        #pragma unroll
        for (int k = 0; k < 4; k++) { ulonglong2 v = p[k]; hhi[2*k] = v.x; hhi[2*k+1] = v.y; }
    }

    if (lane < HH) s_h[lane] = 0.0f;
    __syncwarp();

    float c = 0.0f, afc0 = 0.0f, afc1 = 0.0f, afc2 = 0.0f;

    const float* gx  = g_gates + (size_t)b * TT * G4;
    const float* wf0 = w_fc + (size_t)(lane >> 4) * 3 * (TT * HH) + (lane & 15);

    // depth-4 register ring for gx; depth-1 for FC weights
    float pl[4], ph[4];
    #pragma unroll
    for (int i = 0; i < 4; i++) { pl[i] = gx[i * G4 + glo]; ph[i] = gx[i * G4 + ghi]; }
    float wfa = wf0[0], wfb = wf0[TT * HH], wfc_ = wf0[2 * TT * HH];

    #pragma unroll 4
    for (int t = 0; t < TT; t++) {
        const int sl = t & 3;
        float gxl = pl[sl], gxh = ph[sl];
        if (t + 4 < TT) {
            pl[sl] = gx[(t + 4) * G4 + glo];
            ph[sl] = gx[(t + 4) * G4 + ghi];
        }
        float wa = wfa, wb = wfb, wc = wfc_;
        if (t + 1 < TT) {
            const int to = (t + 1) * HH;
            wfa  = wf0[to];
            wfb  = wf0[to + TT * HH];
            wfc_ = wf0[to + 2 * TT * HH];
        }

        u64 alo0 = pk(gxl, 0.f), alo1 = 0ull;
        u64 ahi0 = pk(gxh, 0.f), ahi1 = 0ull;
        const ulonglong2* hs = (const ulonglong2*)s_h;
        #pragma unroll
        for (int k = 0; k < 4; k++) {
            ulonglong2 hv = hs[k];                     // broadcast LDS.128
            ffma2(alo0, hlo[2*k],   hv.x);
            ffma2(alo1, hlo[2*k+1], hv.y);
            ffma2(ahi0, hhi[2*k],   hv.x);
            ffma2(ahi1, hhi[2*k+1], hv.y);
        }
        float2 qlo = upk(fadd2(alo0, alo1));
        float2 qhi = upk(fadd2(ahi0, ahi1));
        float v_lo = qlo.x + qlo.y;   // i_j (lane<16) | f_j (lane>=16)
        float v_hi = qhi.x + qhi.y;   // g_j (lane<16) | o_j (lane>=16)

        // partner exchange; shfl convergence also orders all lanes' s_h reads
        // (consumed into v_lo/v_hi) before the s_h overwrite below
        float fg = __shfl_sync(0xffffffffu, v_lo, (lane + 16) & 31);
        float og = __shfl_sync(0xffffffffu, v_hi, (lane + 16) & 31);

        const bool lo16 = lane < HH;
        float iv = lo16 ? v_lo : fg;
        float fv = lo16 ? fg   : v_lo;
        float gv = lo16 ? v_hi : og;
        float ov = lo16 ? og   : v_hi;

        c = fast_sig(fv) * c + fast_sig(iv) * fast_tanh(gv);
        float h = fast_sig(ov) * fast_tanh(c);

        if (lo16) s_h[lane] = h;      // value depends on shfl results -> ordered after it
        __syncwarp();                 // h visible before next iteration's LDS

        afc0 = fmaf(h, wa, afc0);
        afc1 = fmaf(h, wb, afc1);
        afc2 = fmaf(h, wc, afc2);
    }

    // reduce FC partials over the 16 hidden units within each half-warp
    #pragma unroll
    for (int off = 8; off >= 1; off >>= 1) {
        afc0 += __shfl_xor_sync(0xffffffffu, afc0, off);
        afc1 += __shfl_xor_sync(0xffffffffu, afc1, off);
        afc2 += __shfl_xor_sync(0xffffffffu, afc2, off);
    }
    if (lane == 0) {
        out[b * NC + 0] = afc0 + b_fc[0];
        out[b * NC + 1] = afc1 + b_fc[1];
        out[b * NC + 2] = afc2 + b_fc[2];
    } else if (lane == 16) {
        out[b * NC + 3] = afc0 + b_fc[3];
        out[b * NC + 4] = afc1 + b_fc[4];
        out[b * NC + 5] = afc2 + b_fc[5];
    }
}

extern "C" void kernel_launch(void* const* d_in, const int* in_sizes, int n_in,
                              void* d_out, int out_size) {
    const float* x    = (const float*)d_in[0];
    const float* w_ih = (const float*)d_in[1];
    const float* w_hh = (const float*)d_in[2];
    const float* b_ih = (const float*)d_in[3];
    const float* b_hh = (const float*)d_in[4];
    const float* w_fc = (const float*)d_in[5];
    const float* b_fc = (const float*)d_in[6];
    float* out = (float*)d_out;

    gates_kernel<<<K1_GRID, 32 * K1_WARPS_PER_BLOCK>>>(x, w_ih, b_ih, b_hh);
    rec_kernel<<<NB, 32>>>(w_hh, w_fc, b_fc, out);
}

// round 8
// speedup vs baseline: 1.1334x; 1.1334x over previous
#include <cuda_runtime.h>

#define TT 512
#define IN 64
#define HH 16
#define NC 6
#define NB 1024
#define G4 64
#define CS 8               /* timesteps per chunk */
#define NCHUNK (TT / CS)   /* 64 */

typedef unsigned long long u64;

__device__ __forceinline__ float fast_tanh(float x) {
    float r; asm("tanh.approx.f32 %0, %1;" : "=f"(r) : "f"(x)); return r;
}
__device__ __forceinline__ float fast_sig(float x) {
    return fmaf(fast_tanh(0.5f * x), 0.5f, 0.5f);
}
__device__ __forceinline__ void ffma2(u64& a, u64 b, u64 c) {
    asm("fma.rn.f32x2 %0, %1, %2, %0;" : "+l"(a) : "l"(b), "l"(c));
}
__device__ __forceinline__ u64 fadd2(u64 a, u64 b) {
    u64 r; asm("add.rn.f32x2 %0, %1, %2;" : "=l"(r) : "l"(a), "l"(b)); return r;
}
__device__ __forceinline__ float2 upk(u64 v) {
    float2 r; asm("mov.b64 {%0, %1}, %2;" : "=f"(r.x), "=f"(r.y) : "l"(v)); return r;
}
__device__ __forceinline__ u64 pk(float x, float y) {
    u64 r; asm("mov.b64 %0, {%1, %2};" : "=l"(r) : "f"(x), "f"(y)); return r;
}

// Block = 1 batch element. Warps 0,1 produce gate pre-activations for the NEXT
// 8-step chunk while warp 2 runs the recurrence on the CURRENT chunk.
// Double buffer + one __syncthreads per phase: no spin-waits, no flags,
// deadlock-free by construction (every thread reaches every barrier).
__global__ __launch_bounds__(96, 7)
void lstm_bsp_kernel(const float* __restrict__ x,
                     const float* __restrict__ w_ih,
                     const float* __restrict__ w_hh,
                     const float* __restrict__ b_ih,
                     const float* __restrict__ b_hh,
                     const float* __restrict__ w_fc,
                     const float* __restrict__ b_fc,
                     float* __restrict__ out)
{
    const int b    = blockIdx.x;
    const int tid  = threadIdx.x;
    const int w    = tid >> 5;
    const int lane = tid & 31;

    __shared__ __align__(16) float buf[2][CS][G4];   // gate chunks (double buffer)
    __shared__ __align__(16) u64   xst[2][32];       // per-producer-warp x staging
    __shared__ __align__(16) float s_h[HH];

    if (tid < HH) s_h[tid] = 0.0f;

    // ---------------- per-warp persistent state ----------------
    // producers (w<2): gate row g = 32*w + lane of w_ih, packed pairs
    u64 wr[32];
    float bias = 0.0f;
    // consumer (w==2): w_hh rows lane and lane+32, packed pairs
    u64 hlo[8], hhi[8];
    float cst = 0.0f, afc0 = 0.0f, afc1 = 0.0f, afc2 = 0.0f;
    const float* wf0 = w_fc;

    const float* xb = x + (size_t)b * TT * IN;

    if (w < 2) {
        const int g = 32 * w + lane;
        const ulonglong2* p = (const ulonglong2*)(w_ih + (size_t)g * IN);
        #pragma unroll
        for (int k = 0; k < 16; k++) { ulonglong2 v = p[k]; wr[2*k] = v.x; wr[2*k+1] = v.y; }
        bias = b_ih[g] + b_hh[g];
    } else {
        const int glo = lane, ghi = lane + 32;
        const ulonglong2* p = (const ulonglong2*)(w_hh + (size_t)glo * HH);
        #pragma unroll
        for (int k = 0; k < 4; k++) { ulonglong2 v = p[k]; hlo[2*k] = v.x; hlo[2*k+1] = v.y; }
        p = (const ulonglong2*)(w_hh + (size_t)ghi * HH);
        #pragma unroll
        for (int k = 0; k < 4; k++) { ulonglong2 v = p[k]; hhi[2*k] = v.x; hhi[2*k+1] = v.y; }
        wf0 = w_fc + (size_t)(lane >> 4) * 3 * (TT * HH) + (lane & 15);
    }

    // ---------------- prologue: producers fill buf[0] with chunk 0 ----------------
    if (w < 2) {
        const int g = 32 * w + lane;
        #pragma unroll
        for (int half = 0; half < 2; half++) {
            u64 xq[4];
            #pragma unroll
            for (int q = 0; q < 4; q++)
                xq[q] = *(const u64*)(xb + (size_t)(half * 4 + q) * G4 + 2 * lane);
            #pragma unroll
            for (int q = 0; q < 4; q++) {
                xst[w][lane] = xq[q];
                __syncwarp();
                u64 a0 = pk(bias, 0.f), a1 = 0ull;
                const ulonglong2* xs = (const ulonglong2*)xst[w];
                #pragma unroll
                for (int k = 0; k < 16; k++) {
                    ulonglong2 xv = xs[k];
                    ffma2(a0, wr[2*k],   xv.x);
                    ffma2(a1, wr[2*k+1], xv.y);
                }
                float2 s2 = upk(fadd2(a0, a1));
                buf[0][half * 4 + q][g] = s2.x + s2.y;
                __syncwarp();
            }
        }
    }
    __syncthreads();

    float wfa = 0.f, wfb = 0.f, wfc_ = 0.f;
    if (w == 2) { wfa = wf0[0]; wfb = wf0[TT * HH]; wfc_ = wf0[2 * TT * HH]; }

    // ---------------- phases ----------------
    for (int ch = 0; ch < NCHUNK; ch++) {
        if (w < 2) {
            // produce chunk ch+1 into buf[(ch+1)&1]
            if (ch + 1 < NCHUNK) {
                const int g = 32 * w + lane;
                float* dst = &buf[(ch + 1) & 1][0][0];
                const int t0 = (ch + 1) * CS;
                #pragma unroll
                for (int half = 0; half < 2; half++) {
                    u64 xq[4];
                    #pragma unroll
                    for (int q = 0; q < 4; q++)
                        xq[q] = *(const u64*)(xb + (size_t)(t0 + half * 4 + q) * G4 + 2 * lane);
                    #pragma unroll
                    for (int q = 0; q < 4; q++) {
                        xst[w][lane] = xq[q];
                        __syncwarp();
                        u64 a0 = pk(bias, 0.f), a1 = 0ull;
                        const ulonglong2* xs = (const ulonglong2*)xst[w];
                        #pragma unroll
                        for (int k = 0; k < 16; k++) {
                            ulonglong2 xv = xs[k];
                            ffma2(a0, wr[2*k],   xv.x);
                            ffma2(a1, wr[2*k+1], xv.y);
                        }
                        float2 s2 = upk(fadd2(a0, a1));
                        dst[(half * 4 + q) * G4 + g] = s2.x + s2.y;
                        __syncwarp();
                    }
                }
            }
        } else {
            // consume chunk ch from buf[ch&1]
            const int glo = lane, ghi = lane + 32;
            const float* src = &buf[ch & 1][0][0];
            #pragma unroll
            for (int q = 0; q < CS; q++) {
                const int t = ch * CS + q;
                float gxl = src[q * G4 + glo];
                float gxh = src[q * G4 + ghi];

                float wa = wfa, wb = wfb, wc = wfc_;
                if (t + 1 < TT) {
                    const int to = (t + 1) * HH;
                    wfa  = wf0[to];
                    wfb  = wf0[to + TT * HH];
                    wfc_ = wf0[to + 2 * TT * HH];
                }

                u64 alo0 = pk(gxl, 0.f), alo1 = 0ull;
                u64 ahi0 = pk(gxh, 0.f), ahi1 = 0ull;
                const ulonglong2* hs = (const ulonglong2*)s_h;
                #pragma unroll
                for (int k = 0; k < 4; k++) {
                    ulonglong2 hv = hs[k];          // broadcast LDS.128
                    ffma2(alo0, hlo[2*k],   hv.x);
                    ffma2(alo1, hlo[2*k+1], hv.y);
                    ffma2(ahi0, hhi[2*k],   hv.x);
                    ffma2(ahi1, hhi[2*k+1], hv.y);
                }
                float2 qlo = upk(fadd2(alo0, alo1));
                float2 qhi = upk(fadd2(ahi0, ahi1));
                float v_lo = qlo.x + qlo.y;   // i_j (lane<16) | f_j (lane>=16)
                float v_hi = qhi.x + qhi.y;   // g_j (lane<16) | o_j (lane>=16)

                float fg = __shfl_sync(0xffffffffu, v_lo, (lane + 16) & 31);
                float og = __shfl_sync(0xffffffffu, v_hi, (lane + 16) & 31);

                const bool lo16 = lane < HH;
                float iv = lo16 ? v_lo : fg;
                float fv = lo16 ? fg   : v_lo;
                float gv = lo16 ? v_hi : og;
                float ov = lo16 ? og   : v_hi;

                cst = fast_sig(fv) * cst + fast_sig(iv) * fast_tanh(gv);
                float h = fast_sig(ov) * fast_tanh(cst);

                if (lo16) s_h[lane] = h;   // ordered after shfl (dataflow)
                __syncwarp();              // visible before next step's LDS

                afc0 = fmaf(h, wa, afc0);
                afc1 = fmaf(h, wb, afc1);
                afc2 = fmaf(h, wc, afc2);
            }
        }
        __syncthreads();   // phase barrier: buffers swap roles
    }

    // ---------------- epilogue: FC reduction (consumer warp) ----------------
    if (w == 2) {
        #pragma unroll
        for (int off = 8; off >= 1; off >>= 1) {
            afc0 += __shfl_xor_sync(0xffffffffu, afc0, off);
            afc1 += __shfl_xor_sync(0xffffffffu, afc1, off);
            afc2 += __shfl_xor_sync(0xffffffffu, afc2, off);
        }
        if (lane == 0) {
            out[b * NC + 0] = afc0 + b_fc[0];
            out[b * NC + 1] = afc1 + b_fc[1];
            out[b * NC + 2] = afc2 + b_fc[2];
        } else if (lane == 16) {
            out[b * NC + 3] = afc0 + b_fc[3];
            out[b * NC + 4] = afc1 + b_fc[4];
            out[b * NC + 5] = afc2 + b_fc[5];
        }
    }
}

extern "C" void kernel_launch(void* const* d_in, const int* in_sizes, int n_in,
                              void* d_out, int out_size) {
    const float* x    = (const float*)d_in[0];
    const float* w_ih = (const float*)d_in[1];
    const float* w_hh = (const float*)d_in[2];
    const float* b_ih = (const float*)d_in[3];
    const float* b_hh = (const float*)d_in[4];
    const float* w_fc = (const float*)d_in[5];
    const float* b_fc = (const float*)d_in[6];
    float* out = (float*)d_out;

    lstm_bsp_kernel<<<NB, 96>>>(x, w_ih, w_hh, b_ih, b_hh, w_fc, b_fc, out);
}

// round 13
// speedup vs baseline: 1.3874x; 1.2241x over previous
#include <cuda_runtime.h>
#include <cstdint>

#define TT 512
#define IN 64
#define HH 16
#define NC 6
#define NB 1024
#define G4 64
#define CS 8               /* timesteps per chunk */
#define NCHUNK (TT / CS)   /* 64 */
#define CHUNK_BYTES (CS * IN * 4)   /* 2048 */

typedef unsigned long long u64;
typedef unsigned int u32;

__device__ __forceinline__ float fast_tanh(float x) {
    float r; asm("tanh.approx.f32 %0, %1;" : "=f"(r) : "f"(x)); return r;
}
__device__ __forceinline__ float fast_sig(float x) {
    return fmaf(fast_tanh(0.5f * x), 0.5f, 0.5f);
}
__device__ __forceinline__ void ffma2(u64& a, u64 b, u64 c) {
    asm("fma.rn.f32x2 %0, %1, %2, %0;" : "+l"(a) : "l"(b), "l"(c));
}
__device__ __forceinline__ u64 fadd2(u64 a, u64 b) {
    u64 r; asm("add.rn.f32x2 %0, %1, %2;" : "=l"(r) : "l"(a), "l"(b)); return r;
}
__device__ __forceinline__ float2 upk(u64 v) {
    float2 r; asm("mov.b64 {%0, %1}, %2;" : "=f"(r.x), "=f"(r.y) : "l"(v)); return r;
}
__device__ __forceinline__ u64 pk(float x, float y) {
    u64 r; asm("mov.b64 %0, {%1, %2};" : "=l"(r) : "f"(x), "f"(y)); return r;
}
__device__ __forceinline__ void cp_async16(u32 smem_dst, const void* gsrc) {
    asm volatile("cp.async.cg.shared.global [%0], [%1], 16;" :: "r"(smem_dst), "l"(gsrc));
}
__device__ __forceinline__ void cp_commit() {
    asm volatile("cp.async.commit_group;" ::: "memory");
}
__device__ __forceinline__ void cp_wait_all() {
    asm volatile("cp.async.wait_group 0;" ::: "memory");
}

// Block = 1 batch element. Warps 0,1: gate producers (lane owns gate g = tid,
// full w_ih row in regs). Warp 2: recurrence consumer. Double-buffered gate
// chunks + double-buffered cp.async x chunks; one __syncthreads per phase.
// No spin-waits; sync topology identical to the R8 kernel that executed.
// Producer register budget ~84 < 97 cap (occ 7) -> weights stay resident.
__global__ __launch_bounds__(96, 7)
void lstm_bsp2_kernel(const float* __restrict__ x,
                      const float* __restrict__ w_ih,
                      const float* __restrict__ w_hh,
                      const float* __restrict__ b_ih,
                      const float* __restrict__ b_hh,
                      const float* __restrict__ w_fc,
                      const float* __restrict__ b_fc,
                      float* __restrict__ out)
{
    const int b    = blockIdx.x;
    const int tid  = threadIdx.x;
    const int w    = tid >> 5;
    const int lane = tid & 31;

    __shared__ __align__(16) float xbuf[2][CS * IN];   // x chunks (cp.async dest)
    __shared__ __align__(16) float gbuf[2][CS][G4];    // gate pre-activations
    __shared__ __align__(16) float s_h[HH];

    if (tid < HH) s_h[tid] = 0.0f;

    const float* xb = x + (size_t)b * TT * IN;

    // ---------------- per-warp persistent state ----------------
    u64 wr[32];            // producers: packed w_ih row of gate g = tid
    float bias = 0.0f;
    u64 hlo[8], hhi[8];    // consumer: packed w_hh rows lane, lane+32
    float cst = 0.0f, afc0 = 0.0f, afc1 = 0.0f, afc2 = 0.0f;
    const float* wf0 = w_fc;

    if (w < 2) {
        const int g = tid;
        const ulonglong2* p = (const ulonglong2*)(w_ih + (size_t)g * IN);
        #pragma unroll
        for (int k = 0; k < 16; k++) { ulonglong2 v = p[k]; wr[2*k] = v.x; wr[2*k+1] = v.y; }
        bias = b_ih[g] + b_hh[g];

        // prologue: async-load chunks 0 and 1 into slots 0 and 1
        u32 s0 = (u32)__cvta_generic_to_shared(&xbuf[0][0]);
        u32 s1 = (u32)__cvta_generic_to_shared(&xbuf[1][0]);
        cp_async16(s0 + tid * 16,        (const char*)xb + tid * 16);
        cp_async16(s0 + 1024 + tid * 16, (const char*)xb + 1024 + tid * 16);
        cp_async16(s1 + tid * 16,        (const char*)xb + CHUNK_BYTES + tid * 16);
        cp_async16(s1 + 1024 + tid * 16, (const char*)xb + CHUNK_BYTES + 1024 + tid * 16);
        cp_commit();
        cp_wait_all();
    } else {
        const int glo = lane, ghi = lane + 32;
        const ulonglong2* p = (const ulonglong2*)(w_hh + (size_t)glo * HH);
        #pragma unroll
        for (int k = 0; k < 4; k++) { ulonglong2 v = p[k]; hlo[2*k] = v.x; hlo[2*k+1] = v.y; }
        p = (const ulonglong2*)(w_hh + (size_t)ghi * HH);
        #pragma unroll
        for (int k = 0; k < 4; k++) { ulonglong2 v = p[k]; hhi[2*k] = v.x; hhi[2*k+1] = v.y; }
        wf0 = w_fc + (size_t)(lane >> 4) * 3 * (TT * HH) + (lane & 15);
    }
    __syncthreads();   // chunks 0,1 visible to all producers

    // prologue: producers compute gbuf[0] <- chunk 0
    if (w < 2) {
        const int g = tid;
        #pragma unroll
        for (int q = 0; q < CS; q++) {
            u64 a0 = pk(bias, 0.f), a1 = 0ull;
            const ulonglong2* xs = (const ulonglong2*)&xbuf[0][q * IN];
            #pragma unroll
            for (int k = 0; k < 16; k++) {
                ulonglong2 xv = xs[k];             // broadcast LDS.128
                ffma2(a0, wr[2*k],   xv.x);
                ffma2(a1, wr[2*k+1], xv.y);
            }
            float2 s2 = upk(fadd2(a0, a1));
            gbuf[0][q][g] = s2.x + s2.y;           // conflict-free STS.32
        }
    }
    __syncthreads();

    float wfa = 0.f, wfb = 0.f, wfc_ = 0.f;
    if (w == 2) { wfa = wf0[0]; wfb = wf0[TT * HH]; wfc_ = wf0[2 * TT * HH]; }

    // ---------------- phases ----------------
    for (int ch = 0; ch < NCHUNK; ch++) {
        if (w < 2) {
            // 1) start async load of chunk ch+2 into slot ch&1 (just freed)
            if (ch + 2 < NCHUNK) {
                u32 sd = (u32)__cvta_generic_to_shared(&xbuf[ch & 1][0]);
                const char* gs = (const char*)xb + (size_t)(ch + 2) * CHUNK_BYTES;
                cp_async16(sd + tid * 16,        gs + tid * 16);
                cp_async16(sd + 1024 + tid * 16, gs + 1024 + tid * 16);
            }
            cp_commit();

            // 2) compute gbuf[(ch+1)&1] <- chunk ch+1 (covers the DRAM latency)
            if (ch + 1 < NCHUNK) {
                const int g = tid;
                const float* xc = &xbuf[(ch + 1) & 1][0];
                float* dst = &gbuf[(ch + 1) & 1][0][0];
                #pragma unroll
                for (int q = 0; q < CS; q++) {
                    u64 a0 = pk(bias, 0.f), a1 = 0ull;
                    const ulonglong2* xs = (const ulonglong2*)(xc + q * IN);
                    #pragma unroll
                    for (int k = 0; k < 16; k++) {
                        ulonglong2 xv = xs[k];     // broadcast LDS.128
                        ffma2(a0, wr[2*k],   xv.x);
                        ffma2(a1, wr[2*k+1], xv.y);
                    }
                    float2 s2 = upk(fadd2(a0, a1));
                    dst[q * G4 + g] = s2.x + s2.y;
                }
            }
            // 3) ensure chunk ch+2 landed before the phase barrier publishes it
            cp_wait_all();
        } else {
            // consume chunk ch from gbuf[ch&1]
            const int glo = lane, ghi = lane + 32;
            const float* src = &gbuf[ch & 1][0][0];
            #pragma unroll
            for (int q = 0; q < CS; q++) {
                const int t = ch * CS + q;
                float gxl = src[q * G4 + glo];
                float gxh = src[q * G4 + ghi];

                float wa = wfa, wb = wfb, wc = wfc_;
                if (t + 1 < TT) {
                    const int to = (t + 1) * HH;
                    wfa  = wf0[to];
                    wfb  = wf0[to + TT * HH];
                    wfc_ = wf0[to + 2 * TT * HH];
                }

                u64 alo0 = pk(gxl, 0.f), alo1 = 0ull;
                u64 ahi0 = pk(gxh, 0.f), ahi1 = 0ull;
                const ulonglong2* hs = (const ulonglong2*)s_h;
                #pragma unroll
                for (int k = 0; k < 4; k++) {
                    ulonglong2 hv = hs[k];          // broadcast LDS.128
                    ffma2(alo0, hlo[2*k],   hv.x);
                    ffma2(alo1, hlo[2*k+1], hv.y);
                    ffma2(ahi0, hhi[2*k],   hv.x);
                    ffma2(ahi1, hhi[2*k+1], hv.y);
                }
                float2 qlo = upk(fadd2(alo0, alo1));
                float2 qhi = upk(fadd2(ahi0, ahi1));
                float v_lo = qlo.x + qlo.y;   // i_j (lane<16) | f_j (lane>=16)
                float v_hi = qhi.x + qhi.y;   // g_j (lane<16) | o_j (lane>=16)

                float fg = __shfl_sync(0xffffffffu, v_lo, (lane + 16) & 31);
                float og = __shfl_sync(0xffffffffu, v_hi, (lane + 16) & 31);

                const bool lo16 = lane < HH;
                float iv = lo16 ? v_lo : fg;
                float fv = lo16 ? fg   : v_lo;
                float gv = lo16 ? v_hi : og;
                float ov = lo16 ? og   : v_hi;

                cst = fast_sig(fv) * cst + fast_sig(iv) * fast_tanh(gv);
                float h = fast_sig(ov) * fast_tanh(cst);

                if (lo16) s_h[lane] = h;   // ordered after shfl (dataflow)
                __syncwarp();              // visible before next step's LDS

                afc0 = fmaf(h, wa, afc0);
                afc1 = fmaf(h, wb, afc1);
                afc2 = fmaf(h, wc, afc2);
            }
        }
        __syncthreads();   // phase barrier: buffers swap roles
    }

    // ---------------- epilogue: FC reduction (consumer warp) ----------------
    if (w == 2) {
        #pragma unroll
        for (int off = 8; off >= 1; off >>= 1) {
            afc0 += __shfl_xor_sync(0xffffffffu, afc0, off);
            afc1 += __shfl_xor_sync(0xffffffffu, afc1, off);
            afc2 += __shfl_xor_sync(0xffffffffu, afc2, off);
        }
        if (lane == 0) {
            out[b * NC + 0] = afc0 + b_fc[0];
            out[b * NC + 1] = afc1 + b_fc[1];
            out[b * NC + 2] = afc2 + b_fc[2];
        } else if (lane == 16) {
            out[b * NC + 3] = afc0 + b_fc[3];
            out[b * NC + 4] = afc1 + b_fc[4];
            out[b * NC + 5] = afc2 + b_fc[5];
        }
    }
}

extern "C" void kernel_launch(void* const* d_in, const int* in_sizes, int n_in,
                              void* d_out, int out_size) {
    const float* x    = (const float*)d_in[0];
    const float* w_ih = (const float*)d_in[1];
    const float* w_hh = (const float*)d_in[2];
    const float* b_ih = (const float*)d_in[3];
    const float* b_hh = (const float*)d_in[4];
    const float* w_fc = (const float*)d_in[5];
    const float* b_fc = (const float*)d_in[6];
    float* out = (float*)d_out;

    lstm_bsp2_kernel<<<NB, 96>>>(x, w_ih, w_hh, b_ih, b_hh, w_fc, b_fc, out);
}